// round 3
// baseline (speedup 1.0000x reference)
#include <cuda_runtime.h>
#include <cuda_fp16.h>
#include <cstdint>

#define E_TOT      100000
#define NCHUNK     65
#define B_TILE     16384
#define NTILES     782          /* ceil(100000/128) */

/* ---- tcgen05-path smem layout (relative to 1024-aligned base) ---- */
#define SM_A0      0
#define SM_A1      32768
#define SM_B       65536        /* 4 x 16384 */
#define SM_V       131072       /* 128 rows x 72 floats = 36864 B */
#define SM_TPTR    167936
#define SM_MB_B    167952       /* 4 x 8B mbarriers: W-chunk full   */
#define SM_MB_D    167984       /* 4 x 8B mbarriers: mma committed  */
#define SM_END     168016

/* ---- fallback-path smem layout (relative to same base) ---- */
#define FB_X       0            /* f32 [128 k][132]  = 67584 B  */
#define FB_V       67584        /* f32 [64 v][132]   = 33792 B  */
#define FB_B       101376       /* f32 [2][64 m][132]= 67584 B  */
#define FB_S       168960       /* f32 [64 v][64 m]  = 16384 B  */

#define SMEM_DYN   (200 * 1024)

/* does this device pass have tcgen05 (arch-specific sm_103a/sm_100a)? */
#if !defined(__CUDA_ARCH__)
#  define TCPATH 1   /* host pass: parse the tcgen05 branch (not codegen'd) */
#elif defined(__CUDA_ARCH_FEAT_SM103_ALL) || defined(__CUDA_ARCH_FEAT_SM100_ALL) || \
      defined(__CUDA_ARCH_FEAT_SM101_ALL) || defined(__CUDA_ARCH_SPECIFIC__)
#  define TCPATH 1
#else
#  define TCPATH 0
#endif

/* pre-swizzled fp16 W' image: 65 chunks of [64 n x 128 k] blocked SW128 */
__device__ __align__(16) unsigned char g_Wimg[NCHUNK * B_TILE];

/* ---------------- generic helpers ---------------- */

__device__ __forceinline__ uint32_t sw128(uint32_t x) { return x ^ ((x >> 3) & 0x70u); }

__device__ __forceinline__ uint32_t smem_u32(const void* p) {
    uint32_t a;
    asm("{ .reg .u64 t; cvta.to.shared.u64 t, %1; cvt.u32.u64 %0, t; }" : "=r"(a) : "l"(p));
    return a;
}

/* pack two f32 -> f16x2; 'lo' lands in the low (memory-first) half */
__device__ __forceinline__ uint32_t pack_h2(float lo, float hi) {
    uint32_t r;
    asm("cvt.rn.f16x2.f32 %0, %1, %2;" : "=r"(r) : "f"(hi), "f"(lo));
    return r;
}

__device__ __forceinline__ void sts128(uint32_t addr, uint32_t a, uint32_t b, uint32_t c, uint32_t d) {
    asm volatile("st.shared.v4.b32 [%0], {%1, %2, %3, %4};"
                 :: "r"(addr), "r"(a), "r"(b), "r"(c), "r"(d) : "memory");
}
__device__ __forceinline__ float lds_f32(uint32_t addr) {
    float v;
    asm volatile("ld.shared.f32 %0, [%1];" : "=f"(v) : "r"(addr));
    return v;
}

/* ---------------- prep kernel: pre-swizzled fp16 W' image ---------------- */
/* chunk c<64: Wc[n,k] = W[n*64+c, k]; chunk 64: Wc[n,k] = (k<64)? b[n*64+k] : 0 */
__global__ void prep_w(const float* __restrict__ W, const float* __restrict__ b) {
    uint32_t gid = blockIdx.x * 256u + threadIdx.x;      /* 0 .. 266239 */
    uint32_t c  = gid >> 12;
    uint32_t r  = gid & 4095u;
    uint32_t n  = r >> 6;
    uint32_t k  = (r & 63u) * 2u;
    float w0, w1;
    if (c < 64u) {
        const float* s = W + ((n * 64u + c) * 128u + k);
        w0 = s[0]; w1 = s[1];
    } else if (k < 64u) {
        w0 = b[n * 64u + k]; w1 = b[n * 64u + k + 1u];
    } else {
        w0 = 0.f; w1 = 0.f;
    }
    uint32_t off = ((n >> 3) + (k >> 6) * 8u) * 1024u + (n & 7u) * 128u + (k & 63u) * 2u;
    *(uint32_t*)(g_Wimg + c * B_TILE + sw128(off)) = pack_h2(w0, w1);
}

/* ---------------- main kernel ---------------- */
__global__ void __launch_bounds__(256, 1)
edge_msg_main(const float* __restrict__ vert,
              const float* __restrict__ xedges,
              const float* __restrict__ Wg,
              const float* __restrict__ bg,
              float* __restrict__ out)
{
    extern __shared__ unsigned char smem_raw[];
    const uint32_t raw  = smem_u32(smem_raw);
    const uint32_t base = (raw + 1023u) & ~1023u;
    unsigned char* sb   = smem_raw + (base - raw);

    const int tid  = threadIdx.x;
    const int tb   = blockIdx.x * 128;

#if TCPATH
    /* ================= tcgen05 path (sm_103a) ================= */
    const int wid  = tid >> 5;
    const int lane = tid & 31;

    (void)Wg; (void)bg;

    if (tid == 0) {
        #pragma unroll
        for (int i = 0; i < 4; i++) {
            asm volatile("mbarrier.init.shared.b64 [%0], 1;" :: "r"(base + SM_MB_B + i * 8) : "memory");
            asm volatile("mbarrier.init.shared.b64 [%0], 1;" :: "r"(base + SM_MB_D + i * 8) : "memory");
        }
    }
    if (wid == 0) {
        asm volatile("tcgen05.alloc.cta_group::1.sync.aligned.shared::cta.b32 [%0], 512;"
                     :: "r"(base + SM_TPTR) : "memory");
        asm volatile("tcgen05.relinquish_alloc_permit.cta_group::1.sync.aligned;");
    }
    __syncthreads();
    uint32_t tmem;
    asm volatile("ld.shared.b32 %0, [%1];" : "=r"(tmem) : "r"(base + SM_TPTR));

    bool is_elect = false;
    {
        uint32_t p;
        asm volatile("{\n\t.reg .pred P;\n\telect.sync _|P, 0xFFFFFFFF;\n\tselp.b32 %0, 1, 0, P;\n\t}" : "=r"(p));
        is_elect = (wid == 0) && (p != 0);
    }

    /* prefetch W chunks 0,1 */
    if (is_elect) {
        #pragma unroll
        for (int j = 0; j < 2; j++) {
            asm volatile("mbarrier.arrive.expect_tx.shared.b64 _, [%0], %1;"
                         :: "r"(base + SM_MB_B + j * 8), "r"((uint32_t)B_TILE) : "memory");
            asm volatile("cp.async.bulk.shared::cta.global.mbarrier::complete_tx::bytes [%0], [%1], %2, [%3];"
                         :: "r"(base + SM_B + j * B_TILE), "l"(g_Wimg + j * B_TILE),
                            "r"((uint32_t)B_TILE), "r"(base + SM_MB_B + j * 8) : "memory");
        }
    }

    /* stage vertices: 128 rows x 64 f32, row stride 288 B (72 floats) */
    {
        const uint32_t vb = base + SM_V;
        for (int i = tid; i < 128 * 16; i += 256) {
            int r  = i >> 4;
            int v4 = i & 15;
            int e  = tb + r; if (e >= E_TOT) e = E_TOT - 1;
            const float4 val = *(const float4*)(vert + (size_t)e * 64 + v4 * 4);
            sts128(vb + (uint32_t)(r * 288 + v4 * 16),
                   __float_as_uint(val.x), __float_as_uint(val.y),
                   __float_as_uint(val.z), __float_as_uint(val.w));
        }
    }

    /* edge rows into registers + swizzled A offsets */
    float    xr[64];
    uint32_t offs[8];
    uint32_t srow[8];
    #pragma unroll
    for (int idx = 0; idx < 8; idx++) {
        uint32_t unit = (uint32_t)(idx * 32 + lane);
        uint32_t row  = ((uint32_t)wid << 4) + (unit >> 4);
        uint32_t k8   = (unit & 15u) << 3;
        uint32_t off  = ((row >> 3) + (k8 >> 6) * 16u) * 1024u + (row & 7u) * 128u + (k8 & 63u) * 2u;
        offs[idx] = sw128(off);
        srow[idx] = row * 288u;
        int e = tb + (int)row; if (e >= E_TOT) e = E_TOT - 1;
        const float4* s = (const float4*)(xedges + (size_t)e * 128 + k8);
        float4 a = s[0], c = s[1];
        xr[idx*8+0]=a.x; xr[idx*8+1]=a.y; xr[idx*8+2]=a.z; xr[idx*8+3]=a.w;
        xr[idx*8+4]=c.x; xr[idx*8+5]=c.y; xr[idx*8+6]=c.z; xr[idx*8+7]=c.w;
    }
    __syncthreads();

    const uint32_t vbase = base + SM_V;
    /* smem desc base: SW128, version=1, SBO=64, LBO=1 */
    const uint64_t DBASE = (uint64_t(2) << 61) | (uint64_t(1) << 46) |
                           (uint64_t(64) << 32) | (uint64_t(1) << 16);

    for (int j = 0; j < NCHUNK; j++) {
        if (j >= 2) {
            int pj = j - 2;
            uint32_t mb = base + SM_MB_D + (pj & 3) * 8;
            uint32_t ph = (pj >> 2) & 1;
            asm volatile(
                "{\n\t.reg .pred P;\n\tWL1_%=:\n\t"
                "mbarrier.try_wait.parity.acquire.cta.shared::cta.b64 P, [%0], %1, 0x989680;\n\t"
                "@P bra.uni WD1_%=;\n\tbra.uni WL1_%=;\n\tWD1_%=:\n\t}"
                :: "r"(mb), "r"(ph) : "memory");
        }
        const uint32_t aAddr = base + ((j & 1) ? SM_A1 : SM_A0);

        if (j < 64) {
            #pragma unroll
            for (int idx = 0; idx < 8; idx++) {
                float s = lds_f32(vbase + srow[idx] + (uint32_t)j * 4u);
                sts128(aAddr + offs[idx],
                       pack_h2(xr[idx*8+0]*s, xr[idx*8+1]*s),
                       pack_h2(xr[idx*8+2]*s, xr[idx*8+3]*s),
                       pack_h2(xr[idx*8+4]*s, xr[idx*8+5]*s),
                       pack_h2(xr[idx*8+6]*s, xr[idx*8+7]*s));
            }
        } else {
            /* bias chunk: A[e,k] = (k<64)? fp16(vert[e,k]) : 0 */
            #pragma unroll
            for (int idx = 0; idx < 8; idx++) {
                uint32_t u16 = (uint32_t)(idx * 32 + lane) & 15u;
                uint32_t h0 = 0, h1 = 0, h2 = 0, h3 = 0;
                if (u16 < 8u) {
                    uint32_t va = vbase + srow[idx] + (u16 << 3) * 4u;
                    h0 = pack_h2(lds_f32(va +  0), lds_f32(va +  4));
                    h1 = pack_h2(lds_f32(va +  8), lds_f32(va + 12));
                    h2 = pack_h2(lds_f32(va + 16), lds_f32(va + 20));
                    h3 = pack_h2(lds_f32(va + 24), lds_f32(va + 28));
                }
                sts128(aAddr + offs[idx], h0, h1, h2, h3);
            }
        }
        asm volatile("fence.proxy.async.shared::cta;" ::: "memory");
        __syncthreads();

        if (is_elect) {
            uint32_t mbB = base + SM_MB_B + (j & 3) * 8;
            uint32_t phB = (j >> 2) & 1;
            asm volatile(
                "{\n\t.reg .pred P;\n\tWL2_%=:\n\t"
                "mbarrier.try_wait.parity.acquire.cta.shared::cta.b64 P, [%0], %1, 0x989680;\n\t"
                "@P bra.uni WD2_%=;\n\tbra.uni WL2_%=;\n\tWD2_%=:\n\t}"
                :: "r"(mbB), "r"(phB) : "memory");

            const uint64_t adesc = DBASE | ((uint64_t)(aAddr >> 4) & 0x3FFFull);
            const uint64_t bdesc = DBASE |
                ((uint64_t)((base + SM_B + (uint32_t)(j & 3) * B_TILE) >> 4) & 0x3FFFull);
            #pragma unroll
            for (int kk = 0; kk < 8; kk++) {
                uint64_t ad = adesc + (uint64_t)((kk >> 2) * 1024 + (kk & 3) * 2);
                uint64_t bd = bdesc + (uint64_t)((kk >> 2) * 512  + (kk & 3) * 2);
                uint32_t en = ((j > 0) || (kk > 0)) ? 1u : 0u;
                asm volatile(
                    "{\n\t.reg .pred p;\n\tsetp.ne.u32 p, %5, 0;\n\t"
                    "tcgen05.mma.cta_group::1.kind::f16 [%0], %1, %2, %3, {%4, %4, %4, %4}, p;\n\t}"
                    :: "r"(tmem), "l"(ad), "l"(bd), "r"(0x08100010u), "r"(0u), "r"(en) : "memory");
            }
            asm volatile("tcgen05.commit.cta_group::1.mbarrier::arrive::one.shared::cluster.b64 [%0];"
                         :: "r"(base + SM_MB_D + (j & 3) * 8) : "memory");
            int nj = j + 2;
            if (nj < NCHUNK) {
                asm volatile("mbarrier.arrive.expect_tx.shared.b64 _, [%0], %1;"
                             :: "r"(base + SM_MB_B + (nj & 3) * 8), "r"((uint32_t)B_TILE) : "memory");
                asm volatile("cp.async.bulk.shared::cta.global.mbarrier::complete_tx::bytes [%0], [%1], %2, [%3];"
                             :: "r"(base + SM_B + (uint32_t)(nj & 3) * B_TILE),
                                "l"(g_Wimg + (size_t)nj * B_TILE),
                                "r"((uint32_t)B_TILE),
                                "r"(base + SM_MB_B + (nj & 3) * 8) : "memory");
            }
        }
    }

    /* wait last chunk, read D, store */
    {
        uint32_t mb = base + SM_MB_D + ((NCHUNK - 1) & 3) * 8;
        uint32_t ph = ((NCHUNK - 1) >> 2) & 1;
        asm volatile(
            "{\n\t.reg .pred P;\n\tWL3_%=:\n\t"
            "mbarrier.try_wait.parity.acquire.cta.shared::cta.b64 P, [%0], %1, 0x989680;\n\t"
            "@P bra.uni WD3_%=;\n\tbra.uni WL3_%=;\n\tWD3_%=:\n\t}"
            :: "r"(mb), "r"(ph) : "memory");
    }
    asm volatile("tcgen05.fence::after_thread_sync;" ::: "memory");

    if (wid < 4) {
        uint32_t d[64];
        #pragma unroll
        for (int hb = 0; hb < 2; hb++) {
            uint32_t* r = d + hb * 32;
            asm volatile(
                "tcgen05.ld.sync.aligned.32x32b.x32.b32 "
                "{%0, %1, %2, %3, %4, %5, %6, %7, "
                " %8, %9, %10, %11, %12, %13, %14, %15, "
                " %16, %17, %18, %19, %20, %21, %22, %23, "
                " %24, %25, %26, %27, %28, %29, %30, %31}, [%32];"
                : "=r"(r[0]),  "=r"(r[1]),  "=r"(r[2]),  "=r"(r[3]),
                  "=r"(r[4]),  "=r"(r[5]),  "=r"(r[6]),  "=r"(r[7]),
                  "=r"(r[8]),  "=r"(r[9]),  "=r"(r[10]), "=r"(r[11]),
                  "=r"(r[12]), "=r"(r[13]), "=r"(r[14]), "=r"(r[15]),
                  "=r"(r[16]), "=r"(r[17]), "=r"(r[18]), "=r"(r[19]),
                  "=r"(r[20]), "=r"(r[21]), "=r"(r[22]), "=r"(r[23]),
                  "=r"(r[24]), "=r"(r[25]), "=r"(r[26]), "=r"(r[27]),
                  "=r"(r[28]), "=r"(r[29]), "=r"(r[30]), "=r"(r[31])
                : "r"(tmem + hb * 32));
        }
        asm volatile("tcgen05.wait::ld.sync.aligned;" ::: "memory");
        int e = tb + wid * 32 + lane;
        if (e < E_TOT) {
            float4* dst = (float4*)(out + (size_t)e * 64);
            #pragma unroll
            for (int c4 = 0; c4 < 16; c4++) {
                float4 v;
                v.x = __uint_as_float(d[c4 * 4 + 0]);
                v.y = __uint_as_float(d[c4 * 4 + 1]);
                v.z = __uint_as_float(d[c4 * 4 + 2]);
                v.w = __uint_as_float(d[c4 * 4 + 3]);
                dst[c4] = v;
            }
        }
    }
    __syncthreads();
    if (wid == 0) {
        asm volatile("tcgen05.dealloc.cta_group::1.sync.aligned.b32 %0, 512;" :: "r"(tmem));
    }

#else
    /* ================= fallback path (plain sm_103, fp32 FFMA) ================= */
    float* Xs  = (float*)(sb + FB_X);    /* [128 k][132] */
    float* Vs  = (float*)(sb + FB_V);    /* [64 v][132]  */
    float* Bs  = (float*)(sb + FB_B);    /* [2][64 m][132] */
    float* Bsm = (float*)(sb + FB_S);    /* [64 v][64 m] */

    /* stage X transposed: Xs[k][e] */
    for (int i = tid; i < 128 * 128; i += 256) {
        int e = i >> 7, k = i & 127;
        int ge = tb + e; if (ge >= E_TOT) ge = E_TOT - 1;
        Xs[k * 132 + e] = xedges[(size_t)ge * 128 + k];
    }
    /* stage vert transposed: Vs[v][e] */
    for (int i = tid; i < 128 * 64; i += 256) {
        int e = i >> 6, v = i & 63;
        int ge = tb + e; if (ge >= E_TOT) ge = E_TOT - 1;
        Vs[v * 132 + e] = vert[(size_t)ge * 64 + v];
    }
    /* stage bias: Bsm[v][m] = b[m*64+v] */
    for (int i = tid; i < 4096; i += 256) {
        int v = i & 63, m = i >> 6;
        Bsm[v * 64 + m] = bg[m * 64 + v];
    }

    const int ebk = tid & 31;   /* e-block: edges ebk*4 .. +3 */
    const int mb  = tid >> 5;   /* m-block: outputs mb*8 .. +7 */
    float acc[4][8];
    #pragma unroll
    for (int i = 0; i < 4; i++)
        #pragma unroll
        for (int jj = 0; jj < 8; jj++) acc[i][jj] = 0.f;

    /* cp.async stage of W slice for vertex-dim v into buffer buf */
    auto issueW = [&](int v, int buf) {
        uint32_t dbase = base + FB_B + (uint32_t)buf * 33792u;
        for (int c = tid; c < 2048; c += 256) {
            int m = c >> 5, k4 = c & 31;
            const float* src = Wg + ((size_t)(m * 64 + v)) * 128 + k4 * 4;
            uint32_t dst = dbase + (uint32_t)(m * 528 + k4 * 16);
            asm volatile("cp.async.ca.shared.global [%0], [%1], 16;" :: "r"(dst), "l"(src) : "memory");
        }
        asm volatile("cp.async.commit_group;" ::: "memory");
    };

    issueW(0, 0);
    __syncthreads();   /* also covers staging visibility */

    for (int v = 0; v < 64; v++) {
        int buf = v & 1;
        if (v + 1 < 64) {
            issueW(v + 1, buf ^ 1);
            asm volatile("cp.async.wait_group 1;" ::: "memory");
        } else {
            asm volatile("cp.async.wait_group 0;" ::: "memory");
        }
        __syncthreads();

        float4 vsv = *(const float4*)(Vs + v * 132 + ebk * 4);
        const float* Bv = Bs + (size_t)buf * 8448 + (size_t)mb * 8 * 132;

        for (int k = 0; k < 128; k++) {
            float4 x4 = *(const float4*)(Xs + k * 132 + ebk * 4);
            float xa0 = x4.x * vsv.x, xa1 = x4.y * vsv.y;
            float xa2 = x4.z * vsv.z, xa3 = x4.w * vsv.w;
            #pragma unroll
            for (int jj = 0; jj < 8; jj++) {
                float bvj = Bv[jj * 132 + k];
                acc[0][jj] += xa0 * bvj;
                acc[1][jj] += xa1 * bvj;
                acc[2][jj] += xa2 * bvj;
                acc[3][jj] += xa3 * bvj;
            }
        }
        __syncthreads();
    }

    /* bias */
    for (int v = 0; v < 64; v++) {
        float4 vsv = *(const float4*)(Vs + v * 132 + ebk * 4);
        #pragma unroll
        for (int jj = 0; jj < 8; jj++) {
            float bb = Bsm[v * 64 + mb * 8 + jj];
            acc[0][jj] += vsv.x * bb;
            acc[1][jj] += vsv.y * bb;
            acc[2][jj] += vsv.z * bb;
            acc[3][jj] += vsv.w * bb;
        }
    }

    /* store */
    #pragma unroll
    for (int i = 0; i < 4; i++) {
        int e = tb + ebk * 4 + i;
        if (e < E_TOT) {
            #pragma unroll
            for (int jj = 0; jj < 8; jj++)
                out[(size_t)e * 64 + mb * 8 + jj] = acc[i][jj];
        }
    }
#endif
}

/* ---------------- launcher ---------------- */
extern "C" void kernel_launch(void* const* d_in, const int* in_sizes, int n_in,
                              void* d_out, int out_size) {
    const float* vert  = (const float*)d_in[0];  /* [100000, 64]  */
    const float* edges = (const float*)d_in[1];  /* [100000, 128] */
    const float* W     = (const float*)d_in[2];  /* [4096, 128]   */
    const float* b     = (const float*)d_in[3];  /* [4096]        */
    float* out = (float*)d_out;                  /* [100000, 64]  */

    prep_w<<<1040, 256>>>(W, b);

    cudaFuncSetAttribute(edge_msg_main, cudaFuncAttributeMaxDynamicSharedMemorySize, SMEM_DYN);
    edge_msg_main<<<NTILES, 256, SMEM_DYN>>>(vert, edges, W, b, out);
}